// round 4
// baseline (speedup 1.0000x reference)
#include <cuda_runtime.h>
#include <cuda_bf16.h>
#include <cstdint>
#include <cstdio>

#define E_DIM 1024
#define H_DIM 1024
#define VOC   32000
#define T_STEPS 64
#define NBLK  128          // persistent LSTM blocks

// -------- device scratch (no allocs allowed) --------
__device__ float g_X[T_STEPS * E_DIM];          // inputs per step
__device__ float g_hbuf[2 * H_DIM];             // double-buffered hidden state
__device__ float g_hs[T_STEPS * H_DIM];         // all hidden states
__device__ unsigned int g_flags[NBLK];          // barrier arrival flags
__device__ unsigned int g_epoch;                // barrier broadcast epoch
// pre-split, pre-swizzled fc_W and hs (bf16 hi/lo), layout:
//   elem dst = (row*16 + chunk)*64 + (((e>>3) ^ (row&7))<<3) + (e&7)
__device__ __nv_bfloat16 g_Whi[(size_t)VOC * E_DIM];
__device__ __nv_bfloat16 g_Wlo[(size_t)VOC * E_DIM];
__device__ __nv_bfloat16 g_Bhi[T_STEPS * H_DIM];
__device__ __nv_bfloat16 g_Blo[T_STEPS * H_DIM];

__device__ __forceinline__ float sigmoidf_(float x) { return 1.f / (1.f + __expf(-x)); }

// split float4 -> bf16x2 hi pair + lo pair (Dekker: lo = bf16(x - f32(hi)))
__device__ __forceinline__ void split4(float4 a, uint2& hi, uint2& lo) {
    __nv_bfloat162 h0 = __float22bfloat162_rn(make_float2(a.x, a.y));
    __nv_bfloat162 h1 = __float22bfloat162_rn(make_float2(a.z, a.w));
    float2 f0 = __bfloat1622float2(h0);
    float2 f1 = __bfloat1622float2(h1);
    __nv_bfloat162 l0 = __float22bfloat162_rn(make_float2(a.x - f0.x, a.y - f0.y));
    __nv_bfloat162 l1 = __float22bfloat162_rn(make_float2(a.z - f1.x, a.w - f1.y));
    hi.x = *reinterpret_cast<uint32_t*>(&h0);
    hi.y = *reinterpret_cast<uint32_t*>(&h1);
    lo.x = *reinterpret_cast<uint32_t*>(&l0);
    lo.y = *reinterpret_cast<uint32_t*>(&l1);
}

// =====================================================================
// K0: build X, zero barrier state + h buffers
// =====================================================================
__global__ void prep_kernel(const int* __restrict__ captions,
                            const float* __restrict__ features,
                            const float* __restrict__ etab) {
    int t = blockIdx.x;
    const float* src = (t == 0) ? features : (etab + (size_t)captions[t - 1] * E_DIM);
    for (int k = threadIdx.x; k < E_DIM; k += blockDim.x)
        g_X[t * E_DIM + k] = src[k];
    if (t == 0) {
        for (int k = threadIdx.x; k < 2 * H_DIM; k += blockDim.x) g_hbuf[k] = 0.f;
        if (threadIdx.x < NBLK) g_flags[threadIdx.x] = 0u;
        if (threadIdx.x == 0) g_epoch = 0u;
    }
}

// =====================================================================
// K1: split fc_W -> g_Whi/g_Wlo, pre-swizzled. grid=16000 x 256.
// Each thread: one 8-elem group (32B read, 16B+16B write).
// =====================================================================
__global__ void __launch_bounds__(256)
splitW_kernel(const float* __restrict__ fcW) {
    int g = blockIdx.x * 256 + threadIdx.x;     // 0 .. 4,096,000-1
    int row = g >> 7;                            // 128 groups per row
    int gg  = g & 127;
    int c   = gg >> 3;
    int sub = gg & 7;
    const float4* src = (const float4*)(fcW + ((size_t)row << 10) + (c << 6) + (sub << 3));
    float4 a0 = __ldg(src);
    float4 a1 = __ldg(src + 1);
    uint2 h0, l0, h1, l1;
    split4(a0, h0, l0);
    split4(a1, h1, l1);
    size_t dst = ((size_t)row * 16 + c) * 64 + (size_t)((sub ^ (row & 7)) << 3);
    *(uint4*)(g_Whi + dst) = make_uint4(h0.x, h0.y, h1.x, h1.y);
    *(uint4*)(g_Wlo + dst) = make_uint4(l0.x, l0.y, l1.x, l1.y);
}

// =====================================================================
// K2: persistent LSTM. Flag-array barrier; tail splits g_hs -> g_Bhi/lo.
// =====================================================================
__global__ void __launch_bounds__(512, 1)
lstm_kernel(const float* __restrict__ Wih, const float* __restrict__ Whh,
            const float* __restrict__ bih, const float* __restrict__ bhh) {
    __shared__ float Xg_s[T_STEPS * 32];
    __shared__ float partA[16][32];
    __shared__ float gsum_s[32];
    __shared__ float bias_s[32];
    __shared__ float cs[8];

    const int tid = threadIdx.x;
    const int w   = tid >> 5;
    const int l   = tid & 31;
    const int j   = tid & 7;
    const int c   = tid >> 3;
    const int b   = blockIdx.x;
    const int jg  = b * 8 + j;

    if (tid < 32) {
        int g = tid >> 3, jj = tid & 7;
        int row = g * H_DIM + b * 8 + jj;
        bias_s[tid] = bih[row] + bhh[row];
    }
    if (tid < 8) cs[tid] = 0.f;

    float wreg[4][16];

#pragma unroll
    for (int g = 0; g < 4; g++) {
        const float4* p = (const float4*)(Wih + (size_t)(g * H_DIM + jg) * E_DIM + c * 16);
#pragma unroll
        for (int q = 0; q < 4; q++) {
            float4 a = p[q];
            wreg[g][4*q+0] = a.x; wreg[g][4*q+1] = a.y;
            wreg[g][4*q+2] = a.z; wreg[g][4*q+3] = a.w;
        }
    }
    __syncthreads();

    // Phase A: input projections
    for (int t = 0; t < T_STEPS; t++) {
        float xv[16];
        {
            const float4* xp = (const float4*)(g_X + t * E_DIM + c * 16);
#pragma unroll
            for (int q = 0; q < 4; q++) {
                float4 a = xp[q];
                xv[4*q+0] = a.x; xv[4*q+1] = a.y; xv[4*q+2] = a.z; xv[4*q+3] = a.w;
            }
        }
        float part[4];
#pragma unroll
        for (int g = 0; g < 4; g++) {
            float s = 0.f;
#pragma unroll
            for (int i = 0; i < 16; i++) s = fmaf(wreg[g][i], xv[i], s);
            part[g] = s;
        }
#pragma unroll
        for (int g = 0; g < 4; g++) {
            part[g] += __shfl_xor_sync(0xffffffffu, part[g], 8);
            part[g] += __shfl_xor_sync(0xffffffffu, part[g], 16);
        }
        if (l < 8) {
#pragma unroll
            for (int g = 0; g < 4; g++) partA[w][g * 8 + l] = part[g];
        }
        __syncthreads();
        if (tid < 32) {
            float s = 0.f;
#pragma unroll
            for (int ww = 0; ww < 16; ww++) s += partA[ww][tid];
            Xg_s[t * 32 + tid] = s;
        }
        __syncthreads();
    }

#pragma unroll
    for (int g = 0; g < 4; g++) {
        const float4* p = (const float4*)(Whh + (size_t)(g * H_DIM + jg) * H_DIM + c * 16);
#pragma unroll
        for (int q = 0; q < 4; q++) {
            float4 a = p[q];
            wreg[g][4*q+0] = a.x; wreg[g][4*q+1] = a.y;
            wreg[g][4*q+2] = a.z; wreg[g][4*q+3] = a.w;
        }
    }
    __syncthreads();

    // Phase B: recurrence
    for (int t = 0; t < T_STEPS; t++) {
        const float* hrd = g_hbuf + (t & 1) * H_DIM;
        float hv[16];
        {
            const float4* hp = (const float4*)(hrd + c * 16);
#pragma unroll
            for (int q = 0; q < 4; q++) {
                float4 a = __ldcg(hp + q);
                hv[4*q+0] = a.x; hv[4*q+1] = a.y; hv[4*q+2] = a.z; hv[4*q+3] = a.w;
            }
        }
        float part[4];
#pragma unroll
        for (int g = 0; g < 4; g++) {
            float s = 0.f;
#pragma unroll
            for (int i = 0; i < 16; i++) s = fmaf(wreg[g][i], hv[i], s);
            part[g] = s;
        }
#pragma unroll
        for (int g = 0; g < 4; g++) {
            part[g] += __shfl_xor_sync(0xffffffffu, part[g], 8);
            part[g] += __shfl_xor_sync(0xffffffffu, part[g], 16);
        }
        if (l < 8) {
#pragma unroll
            for (int g = 0; g < 4; g++) partA[w][g * 8 + l] = part[g];
        }
        __syncthreads();
        if (tid < 32) {
            float s = 0.f;
#pragma unroll
            for (int ww = 0; ww < 16; ww++) s += partA[ww][tid];
            gsum_s[tid] = s + Xg_s[t * 32 + tid] + bias_s[tid];
        }
        __syncthreads();
        if (tid < 8) {
            float ii = sigmoidf_(gsum_s[tid]);
            float ff = sigmoidf_(gsum_s[8  + tid]);
            float gg = tanhf    (gsum_s[16 + tid]);
            float oo = sigmoidf_(gsum_s[24 + tid]);
            float cc = ff * cs[tid] + ii * gg;
            cs[tid] = cc;
            float hn = oo * tanhf(cc);
            g_hbuf[((t + 1) & 1) * H_DIM + b * 8 + tid] = hn;
            g_hs[t * H_DIM + b * 8 + tid] = hn;
        }
        __syncthreads();

        // ---- flag-array barrier ----
        const unsigned int tgt = (unsigned int)(t + 1);
        if (tid == 0)
            asm volatile("st.release.gpu.u32 [%0], %1;"
                         :: "l"(&g_flags[b]), "r"(tgt) : "memory");
        if (b == 0) {
            if (tid < NBLK) {
                unsigned int v;
                do {
                    asm volatile("ld.acquire.gpu.u32 %0, [%1];"
                                 : "=r"(v) : "l"(&g_flags[tid]) : "memory");
                } while (v < tgt);
            }
            __syncthreads();
            if (tid == 0)
                asm volatile("st.release.gpu.u32 [%0], %1;"
                             :: "l"(&g_epoch), "r"(tgt) : "memory");
        } else {
            if (tid == 0) {
                unsigned int v;
                do {
                    asm volatile("ld.acquire.gpu.u32 %0, [%1];"
                                 : "=r"(v) : "l"(&g_epoch) : "memory");
                } while (v < tgt);
            }
            __syncthreads();
        }
    }

    // ---- tail: split g_hs -> g_Bhi/g_Blo (pre-swizzled), 1 elem/thread ----
    {
        int idx = b * 512 + tid;          // 0..65535
        int t = idx >> 10;
        int e = idx & 1023;
        int cc2 = e >> 6, ee = e & 63;
        float v = __ldcg(&g_hs[t * H_DIM + e]);
        __nv_bfloat16 hb = __float2bfloat16(v);
        float hf = __bfloat162float(hb);
        __nv_bfloat16 lb = __float2bfloat16(v - hf);
        size_t dst = ((size_t)t * 16 + cc2) * 64 + (((ee >> 3) ^ (t & 7)) << 3) + (ee & 7);
        g_Bhi[dst] = hb;
        g_Blo[dst] = lb;
    }
}

// =====================================================================
// K3: fc GEMM — pure bf16 mma.sync m16n8k16, 3-pass split, cp.async
// double-buffered. Tiles land pre-swizzled via linear 16B copies.
// =====================================================================
#define FC_M    128
#define FC_NCH  16                  // K-chunks of 64 fp32 (=128B bf16)

// dynamic smem offsets (bytes)
#define FCB_AHI(b) ((b) * 16384)
#define FCB_ALO(b) (32768 + (b) * 16384)
#define FCB_BHI(b) (65536 + (b) * 8192)
#define FCB_BLO(b) (81920 + (b) * 8192)
#define FC_SMEM    98304

__device__ __forceinline__ uint32_t smem_u32(const void* p) {
    uint32_t a;
    asm("{ .reg .u64 t; cvta.to.shared.u64 t, %1; cvt.u32.u64 %0, t; }" : "=r"(a) : "l"(p));
    return a;
}

#define CP16(dst, src) \
    asm volatile("cp.async.cg.shared.global [%0], [%1], 16;" :: "r"(dst), "l"(src) : "memory")
#define CP_COMMIT() asm volatile("cp.async.commit_group;" ::: "memory")
#define CP_WAIT(n)  asm volatile("cp.async.wait_group %0;" :: "n"(n) : "memory")

#define LDM_X4(r, a)                                                          \
    asm volatile("ldmatrix.sync.aligned.m8n8.x4.shared.b16 {%0,%1,%2,%3}, [%4];" \
        : "=r"((r)[0]), "=r"((r)[1]), "=r"((r)[2]), "=r"((r)[3]) : "r"(a))

#define MMA16816(d, a, b0, b1)                                                \
    asm volatile("mma.sync.aligned.m16n8k16.row.col.f32.bf16.bf16.f32 "       \
        "{%0,%1,%2,%3},{%4,%5,%6,%7},{%8,%9},{%0,%1,%2,%3};"                  \
        : "+f"((d)[0]), "+f"((d)[1]), "+f"((d)[2]), "+f"((d)[3])              \
        : "r"((a)[0]), "r"((a)[1]), "r"((a)[2]), "r"((a)[3]),                 \
          "r"(b0), "r"(b1))

__global__ void __launch_bounds__(128, 2)
fc_mma_kernel(const float* __restrict__ fcb, float* __restrict__ out) {
    extern __shared__ __align__(1024) char smem[];
    const uint32_t sb = smem_u32(smem);

    const int tid  = threadIdx.x;
    const int wid  = tid >> 5;
    const int lane = tid & 31;
    const int vbase = blockIdx.x * FC_M;
    const int m0 = wid * 32;

    // per-lane ldmatrix address pieces (same scheme as round 3)
    const int a_row  = m0 + (lane & 15);
    const uint32_t a_roff = (uint32_t)a_row * 128;
    const uint32_t a_xor  = (uint32_t)(a_row & 7) << 4;
    const uint32_t a_kh   = (uint32_t)(lane >> 4) * 16;
    const int b_rsub = (lane & 7) + ((lane >> 4) & 1) * 8;
    const uint32_t b_xor = (uint32_t)(lane & 7) << 4;
    const uint32_t b_kh  = (uint32_t)((lane >> 3) & 1) * 16;

    float acc[2][8][4];
#pragma unroll
    for (int mt = 0; mt < 2; mt++)
#pragma unroll
        for (int nt = 0; nt < 8; nt++)
#pragma unroll
            for (int q = 0; q < 4; q++) acc[mt][nt][q] = 0.f;

    // stage chunk c into buffer buf (all copies linear: gmem pre-swizzled)
    auto issue = [&](int c, int buf) {
#pragma unroll
        for (int p = 0; p < 16; p++) {           // A: 2048 x 16B
            int idx = tid + p * 128;
            int hl  = idx >> 10;
            int row = (idx >> 3) & 127;
            int seg = idx & 7;
            const char* src = (const char*)(hl ? g_Wlo : g_Whi)
                + (((size_t)(vbase + row) * 16 + c) * 128 + seg * 16);
            uint32_t dst = sb + (hl ? FCB_ALO(buf) : FCB_AHI(buf)) + row * 128 + seg * 16;
            CP16(dst, src);
        }
#pragma unroll
        for (int p = 0; p < 8; p++) {            // B: 1024 x 16B
            int idx = tid + p * 128;
            int hl  = idx >> 9;
            int row = (idx >> 3) & 63;
            int seg = idx & 7;
            const char* src = (const char*)(hl ? g_Blo : g_Bhi)
                + (((size_t)row * 16 + c) * 128 + seg * 16);
            uint32_t dst = sb + (hl ? FCB_BLO(buf) : FCB_BHI(buf)) + row * 128 + seg * 16;
            CP16(dst, src);
        }
        CP_COMMIT();
    };

    issue(0, 0);
    issue(1, 1);

    for (int c = 0; c < FC_NCH; c++) {
        if (c < FC_NCH - 1) { CP_WAIT(1); } else { CP_WAIT(0); }
        __syncthreads();

        const int buf = c & 1;
        const uint32_t sAhi = sb + FCB_AHI(buf);
        const uint32_t sAlo = sb + FCB_ALO(buf);
        const uint32_t sBhi = sb + FCB_BHI(buf);
        const uint32_t sBlo = sb + FCB_BLO(buf);

#pragma unroll
        for (int ks = 0; ks < 4; ks++) {
            const uint32_t akb = (uint32_t)(ks * 32) + a_kh;
            const uint32_t bkb = (uint32_t)(ks * 32) + b_kh;

            uint32_t ah[2][4], al[2][4];
#pragma unroll
            for (int mt = 0; mt < 2; mt++) {
                uint32_t off = a_roff + (uint32_t)(mt * 16 * 128) + (akb ^ a_xor);
                LDM_X4(ah[mt], sAhi + off);
                LDM_X4(al[mt], sAlo + off);
            }
            uint32_t bh[4][4], bl[4][4];
#pragma unroll
            for (int bp = 0; bp < 4; bp++) {
                uint32_t n = (uint32_t)(bp * 16 + b_rsub);
                uint32_t off = n * 128 + (bkb ^ b_xor);
                LDM_X4(bh[bp], sBhi + off);
                LDM_X4(bl[bp], sBlo + off);
            }
#pragma unroll
            for (int mt = 0; mt < 2; mt++)
#pragma unroll
                for (int nt = 0; nt < 8; nt++) {
                    const int bp = nt >> 1, sel = (nt & 1) * 2;
                    MMA16816(acc[mt][nt], ah[mt], bh[bp][sel], bh[bp][sel + 1]);
                    MMA16816(acc[mt][nt], al[mt], bh[bp][sel], bh[bp][sel + 1]);
                    MMA16816(acc[mt][nt], ah[mt], bl[bp][sel], bl[bp][sel + 1]);
                }
        }
        __syncthreads();
        if (c + 2 < FC_NCH) issue(c + 2, buf);
    }

    // epilogue: C[m][n] -> out[n*VOC + vbase+m] + bias
    const int g  = lane >> 2;
    const int t4 = lane & 3;
#pragma unroll
    for (int mt = 0; mt < 2; mt++) {
        int v0 = vbase + m0 + mt * 16 + g;
        float bv0 = fcb[v0];
        float bv8 = fcb[v0 + 8];
#pragma unroll
        for (int nt = 0; nt < 8; nt++) {
            int t0 = nt * 8 + t4 * 2;
            out[(size_t)t0 * VOC + v0]           = acc[mt][nt][0] + bv0;
            out[(size_t)(t0 + 1) * VOC + v0]     = acc[mt][nt][1] + bv0;
            out[(size_t)t0 * VOC + v0 + 8]       = acc[mt][nt][2] + bv8;
            out[(size_t)(t0 + 1) * VOC + v0 + 8] = acc[mt][nt][3] + bv8;
        }
    }
}

// =====================================================================
// launch
// =====================================================================
extern "C" void kernel_launch(void* const* d_in, const int* in_sizes, int n_in,
                              void* d_out, int out_size) {
    const int*   captions = (const int*)  d_in[0];
    const float* features = (const float*)d_in[1];
    const float* etab     = (const float*)d_in[2];
    const float* W_ih     = (const float*)d_in[3];
    const float* W_hh     = (const float*)d_in[4];
    const float* b_ih     = (const float*)d_in[5];
    const float* b_hh     = (const float*)d_in[6];
    const float* fc_W     = (const float*)d_in[7];
    const float* fc_b     = (const float*)d_in[8];
    float* out = (float*)d_out;

    cudaFuncSetAttribute(fc_mma_kernel,
                         cudaFuncAttributeMaxDynamicSharedMemorySize, FC_SMEM);

    prep_kernel<<<T_STEPS, 256>>>(captions, features, etab);
    splitW_kernel<<<(VOC * 128) / 256, 256>>>(fc_W);
    lstm_kernel<<<NBLK, 512>>>(W_ih, W_hh, b_ih, b_hh);
    fc_mma_kernel<<<VOC / FC_M, 128, FC_SMEM>>>(fc_b, out);
}

// round 5
// speedup vs baseline: 1.2649x; 1.2649x over previous
#include <cuda_runtime.h>
#include <cuda_bf16.h>
#include <cstdint>
#include <cstdio>

#define E_DIM 1024
#define H_DIM 1024
#define VOC   32000
#define T_STEPS 64
#define NBLK  128          // persistent LSTM blocks

// -------- device scratch (no allocs allowed) --------
__device__ float g_X[T_STEPS * E_DIM];     // inputs per step
__device__ float g_hbuf[2 * H_DIM];        // double-buffered hidden state
__device__ float g_hs[T_STEPS * H_DIM];    // all hidden states for fc GEMM
__device__ unsigned int g_cnt;             // monotonic barrier counter

__device__ __forceinline__ float sigmoidf_(float x) { return 1.f / (1.f + __expf(-x)); }

// =====================================================================
// K0: build X (features at t=0, embeddings after), zero h buffers + counter
// =====================================================================
__global__ void prep_kernel(const int* __restrict__ captions,
                            const float* __restrict__ features,
                            const float* __restrict__ etab) {
    int t = blockIdx.x;
    const float* src = (t == 0) ? features : (etab + (size_t)captions[t - 1] * E_DIM);
    for (int k = threadIdx.x; k < E_DIM; k += blockDim.x)
        g_X[t * E_DIM + k] = src[k];
    if (t == 0) {
        for (int k = threadIdx.x; k < 2 * H_DIM; k += blockDim.x) g_hbuf[k] = 0.f;
        if (threadIdx.x == 0) g_cnt = 0u;
    }
}

// =====================================================================
// K1: persistent LSTM — round-1 proven version (atomic-counter barrier).
// =====================================================================
__global__ void __launch_bounds__(512, 1)
lstm_kernel(const float* __restrict__ Wih, const float* __restrict__ Whh,
            const float* __restrict__ bih, const float* __restrict__ bhh) {
    __shared__ float Xg_s[T_STEPS * 32];
    __shared__ float partA[16][32];
    __shared__ float gsum_s[32];
    __shared__ float bias_s[32];
    __shared__ float cs[8];

    const int tid = threadIdx.x;
    const int w   = tid >> 5;
    const int l   = tid & 31;
    const int j   = tid & 7;
    const int c   = tid >> 3;
    const int b   = blockIdx.x;
    const int jg  = b * 8 + j;

    if (tid < 32) {
        int g = tid >> 3, jj = tid & 7;
        int row = g * H_DIM + b * 8 + jj;
        bias_s[tid] = bih[row] + bhh[row];
    }
    if (tid < 8) cs[tid] = 0.f;

    float wreg[4][16];

#pragma unroll
    for (int g = 0; g < 4; g++) {
        const float4* p = (const float4*)(Wih + (size_t)(g * H_DIM + jg) * E_DIM + c * 16);
#pragma unroll
        for (int q = 0; q < 4; q++) {
            float4 a = p[q];
            wreg[g][4*q+0] = a.x; wreg[g][4*q+1] = a.y;
            wreg[g][4*q+2] = a.z; wreg[g][4*q+3] = a.w;
        }
    }
    __syncthreads();

    // Phase A: input projections
    for (int t = 0; t < T_STEPS; t++) {
        float xv[16];
        {
            const float4* xp = (const float4*)(g_X + t * E_DIM + c * 16);
#pragma unroll
            for (int q = 0; q < 4; q++) {
                float4 a = xp[q];
                xv[4*q+0] = a.x; xv[4*q+1] = a.y; xv[4*q+2] = a.z; xv[4*q+3] = a.w;
            }
        }
        float part[4];
#pragma unroll
        for (int g = 0; g < 4; g++) {
            float s = 0.f;
#pragma unroll
            for (int i = 0; i < 16; i++) s = fmaf(wreg[g][i], xv[i], s);
            part[g] = s;
        }
#pragma unroll
        for (int g = 0; g < 4; g++) {
            part[g] += __shfl_xor_sync(0xffffffffu, part[g], 8);
            part[g] += __shfl_xor_sync(0xffffffffu, part[g], 16);
        }
        if (l < 8) {
#pragma unroll
            for (int g = 0; g < 4; g++) partA[w][g * 8 + l] = part[g];
        }
        __syncthreads();
        if (tid < 32) {
            float s = 0.f;
#pragma unroll
            for (int ww = 0; ww < 16; ww++) s += partA[ww][tid];
            Xg_s[t * 32 + tid] = s;
        }
        __syncthreads();
    }

#pragma unroll
    for (int g = 0; g < 4; g++) {
        const float4* p = (const float4*)(Whh + (size_t)(g * H_DIM + jg) * H_DIM + c * 16);
#pragma unroll
        for (int q = 0; q < 4; q++) {
            float4 a = p[q];
            wreg[g][4*q+0] = a.x; wreg[g][4*q+1] = a.y;
            wreg[g][4*q+2] = a.z; wreg[g][4*q+3] = a.w;
        }
    }
    __syncthreads();

    // Phase B: recurrence
    for (int t = 0; t < T_STEPS; t++) {
        const float* hrd = g_hbuf + (t & 1) * H_DIM;
        float hv[16];
        {
            const float4* hp = (const float4*)(hrd + c * 16);
#pragma unroll
            for (int q = 0; q < 4; q++) {
                float4 a = __ldcg(hp + q);
                hv[4*q+0] = a.x; hv[4*q+1] = a.y; hv[4*q+2] = a.z; hv[4*q+3] = a.w;
            }
        }
        float part[4];
#pragma unroll
        for (int g = 0; g < 4; g++) {
            float s = 0.f;
#pragma unroll
            for (int i = 0; i < 16; i++) s = fmaf(wreg[g][i], hv[i], s);
            part[g] = s;
        }
#pragma unroll
        for (int g = 0; g < 4; g++) {
            part[g] += __shfl_xor_sync(0xffffffffu, part[g], 8);
            part[g] += __shfl_xor_sync(0xffffffffu, part[g], 16);
        }
        if (l < 8) {
#pragma unroll
            for (int g = 0; g < 4; g++) partA[w][g * 8 + l] = part[g];
        }
        __syncthreads();
        if (tid < 32) {
            float s = 0.f;
#pragma unroll
            for (int ww = 0; ww < 16; ww++) s += partA[ww][tid];
            gsum_s[tid] = s + Xg_s[t * 32 + tid] + bias_s[tid];
        }
        __syncthreads();
        if (tid < 8) {
            float ii = sigmoidf_(gsum_s[tid]);
            float ff = sigmoidf_(gsum_s[8  + tid]);
            float gg = tanhf    (gsum_s[16 + tid]);
            float oo = sigmoidf_(gsum_s[24 + tid]);
            float cc = ff * cs[tid] + ii * gg;
            cs[tid] = cc;
            float hn = oo * tanhf(cc);
            g_hbuf[((t + 1) & 1) * H_DIM + b * 8 + tid] = hn;
            g_hs[t * H_DIM + b * 8 + tid] = hn;
        }
        __syncthreads();
        if (tid == 0) {
            __threadfence();
            atomicAdd(&g_cnt, 1u);
            unsigned int target = (unsigned)NBLK * (unsigned)(t + 1);
            unsigned int v;
            do {
                asm volatile("ld.acquire.gpu.u32 %0, [%1];"
                             : "=r"(v) : "l"(&g_cnt) : "memory");
            } while (v < target);
        }
        __syncthreads();
    }
}

// =====================================================================
// K2: fc GEMM — fused convert + bf16 mma.sync 3-pass split.
//   cp.async stages RAW fp32 W tiles (double-buffered),
//   in-kernel fp32 -> bf16 hi/lo split into SW128 smem,
//   ldmatrix + m16n8k16 HMMA (same proven mma core as round 4).
// Per CTA: M=128 vocab rows, N=64 timesteps, K=1024 in chunks of 64.
// =====================================================================
#define FC_M    128
#define FC_NCH  16

// dynamic smem layout (bytes):
//   Af32[2]  : 2 x 32768  @ 0
//   Abf_hi   : 16384      @ 65536
//   Abf_lo   : 16384      @ 81920
//   Bbf_hi   : 8192       @ 98304
//   Bbf_lo   : 8192       @ 106496
#define FCO_AF32(b) ((b) * 32768)
#define FCO_AHI     65536
#define FCO_ALO     81920
#define FCO_BHI     98304
#define FCO_BLO     106496
#define FC_SMEM     114688      // 112 KB -> 2 CTAs/SM

#define SWZ(x) ((x) ^ (((x) >> 3) & 0x70))

__device__ __forceinline__ uint32_t smem_u32(const void* p) {
    uint32_t a;
    asm("{ .reg .u64 t; cvta.to.shared.u64 t, %1; cvt.u32.u64 %0, t; }" : "=r"(a) : "l"(p));
    return a;
}

// split float2 -> bf16x2 hi + bf16x2 lo (Dekker)
__device__ __forceinline__ void split2(float2 a, uint32_t& hi, uint32_t& lo) {
    __nv_bfloat162 h = __float22bfloat162_rn(a);
    float2 f = __bfloat1622float2(h);
    __nv_bfloat162 l2 = __float22bfloat162_rn(make_float2(a.x - f.x, a.y - f.y));
    hi = *reinterpret_cast<uint32_t*>(&h);
    lo = *reinterpret_cast<uint32_t*>(&l2);
}

#define CP16(dst, src) \
    asm volatile("cp.async.cg.shared.global [%0], [%1], 16;" :: "r"(dst), "l"(src) : "memory")
#define CP_COMMIT() asm volatile("cp.async.commit_group;" ::: "memory")
#define CP_WAIT(n)  asm volatile("cp.async.wait_group %0;" :: "n"(n) : "memory")

#define LDM_X4(r, a)                                                          \
    asm volatile("ldmatrix.sync.aligned.m8n8.x4.shared.b16 {%0,%1,%2,%3}, [%4];" \
        : "=r"((r)[0]), "=r"((r)[1]), "=r"((r)[2]), "=r"((r)[3]) : "r"(a))

#define MMA16816(d, a, b0, b1)                                                \
    asm volatile("mma.sync.aligned.m16n8k16.row.col.f32.bf16.bf16.f32 "       \
        "{%0,%1,%2,%3},{%4,%5,%6,%7},{%8,%9},{%0,%1,%2,%3};"                  \
        : "+f"((d)[0]), "+f"((d)[1]), "+f"((d)[2]), "+f"((d)[3])              \
        : "r"((a)[0]), "r"((a)[1]), "r"((a)[2]), "r"((a)[3]),                 \
          "r"(b0), "r"(b1))

__global__ void __launch_bounds__(128, 2)
fc_mma_kernel(const float* __restrict__ fcW, const float* __restrict__ fcb,
              float* __restrict__ out) {
    extern __shared__ __align__(1024) char smem[];
    const uint32_t sb = smem_u32(smem);

    const int tid  = threadIdx.x;
    const int wid  = tid >> 5;
    const int lane = tid & 31;
    const int vbase = blockIdx.x * FC_M;
    const int m0 = wid * 32;

    // per-lane ldmatrix address pieces (proven scheme)
    const int a_row  = m0 + (lane & 15);
    const uint32_t a_roff = (uint32_t)a_row * 128;
    const uint32_t a_xor  = (uint32_t)(a_row & 7) << 4;
    const uint32_t a_kh   = (uint32_t)(lane >> 4) * 16;
    const int b_rsub = (lane & 7) + ((lane >> 4) & 1) * 8;
    const uint32_t b_xor = (uint32_t)(lane & 7) << 4;
    const uint32_t b_kh  = (uint32_t)((lane >> 3) & 1) * 16;

    float acc[2][8][4];
#pragma unroll
    for (int mt = 0; mt < 2; mt++)
#pragma unroll
        for (int nt = 0; nt < 8; nt++)
#pragma unroll
            for (int q = 0; q < 4; q++) acc[mt][nt][q] = 0.f;

    // issue cp.async for chunk c's fp32 A tile into f32 buffer (c&1)
    auto issue = [&](int c) {
        const uint32_t dbase = sb + FCO_AF32(c & 1);
#pragma unroll
        for (int p = 0; p < 16; p++) {
            int idx = tid + p * 128;        // 0..2047: row = idx>>4, seg = idx&15
            int row = idx >> 4, seg = idx & 15;
            const char* src = (const char*)(fcW + (size_t)(vbase + row) * E_DIM + c * 64)
                              + seg * 16;
            CP16(dbase + (uint32_t)(row * 256 + seg * 16), src);
        }
        CP_COMMIT();
    };

    issue(0);
    issue(1);

    for (int c = 0; c < FC_NCH; c++) {
        if (c < FC_NCH - 1) { CP_WAIT(1); } else { CP_WAIT(0); }
        __syncthreads();   // f32 buf (c&1) ready; all warps past previous mma

        // ---- convert A: f32 smem -> bf16 hi/lo smem (SW128) ----
        {
            const char* af = smem + FCO_AF32(c & 1);
#pragma unroll
            for (int p = 0; p < 32; p++) {
                int fidx = tid + p * 128;        // float2 index, 0..4095
                int row = fidx >> 5, kp = fidx & 31;
                float2 a = *(const float2*)(af + row * 256 + kp * 8);
                uint32_t hi, lo; split2(a, hi, lo);
                uint32_t off = SWZ((uint32_t)(row * 128 + kp * 4));
                *(uint32_t*)(smem + FCO_AHI + off) = hi;
                *(uint32_t*)(smem + FCO_ALO + off) = lo;
            }
        }
        // ---- convert B: g_hs (L2-hot) -> bf16 hi/lo smem ----
        {
#pragma unroll
            for (int p = 0; p < 16; p++) {
                int fidx = tid + p * 128;        // 0..2047
                int row = fidx >> 5, kp = fidx & 31;
                float2 a = *(const float2*)(g_hs + row * H_DIM + c * 64 + kp * 2);
                uint32_t hi, lo; split2(a, hi, lo);
                uint32_t off = SWZ((uint32_t)(row * 128 + kp * 4));
                *(uint32_t*)(smem + FCO_BHI + off) = hi;
                *(uint32_t*)(smem + FCO_BLO + off) = lo;
            }
        }
        __syncthreads();   // bf16 tiles ready; f32 buf consumed

        if (c + 2 < FC_NCH) issue(c + 2);

        // ---- mma over 4 k16-steps (single bf16 buffer) ----
        const uint32_t sAhi = sb + FCO_AHI, sAlo = sb + FCO_ALO;
        const uint32_t sBhi = sb + FCO_BHI, sBlo = sb + FCO_BLO;
#pragma unroll
        for (int ks = 0; ks < 4; ks++) {
            const uint32_t akb = (uint32_t)(ks * 32) + a_kh;
            const uint32_t bkb = (uint32_t)(ks * 32) + b_kh;

            uint32_t ah[2][4], al[2][4];
#pragma unroll
            for (int mt = 0; mt < 2; mt++) {
                uint32_t off = a_roff + (uint32_t)(mt * 16 * 128) + (akb ^ a_xor);
                LDM_X4(ah[mt], sAhi + off);
                LDM_X4(al[mt], sAlo + off);
            }
            uint32_t bh[4][4], bl[4][4];
#pragma unroll
            for (int bp = 0; bp < 4; bp++) {
                uint32_t n = (uint32_t)(bp * 16 + b_rsub);
                uint32_t off = n * 128 + (bkb ^ b_xor);
                LDM_X4(bh[bp], sBhi + off);
                LDM_X4(bl[bp], sBlo + off);
            }
#pragma unroll
            for (int mt = 0; mt < 2; mt++)
#pragma unroll
                for (int nt = 0; nt < 8; nt++) {
                    const int bp = nt >> 1, sel = (nt & 1) * 2;
                    MMA16816(acc[mt][nt], ah[mt], bh[bp][sel], bh[bp][sel + 1]);
                    MMA16816(acc[mt][nt], al[mt], bh[bp][sel], bh[bp][sel + 1]);
                    MMA16816(acc[mt][nt], ah[mt], bl[bp][sel], bl[bp][sel + 1]);
                }
        }
    }

    // epilogue: C[m][n] -> out[n*VOC + vbase+m] + bias
    const int g  = lane >> 2;
    const int t4 = lane & 3;
#pragma unroll
    for (int mt = 0; mt < 2; mt++) {
        int v0 = vbase + m0 + mt * 16 + g;
        float bv0 = fcb[v0];
        float bv8 = fcb[v0 + 8];
#pragma unroll
        for (int nt = 0; nt < 8; nt++) {
            int t0 = nt * 8 + t4 * 2;
            out[(size_t)t0 * VOC + v0]           = acc[mt][nt][0] + bv0;
            out[(size_t)(t0 + 1) * VOC + v0]     = acc[mt][nt][1] + bv0;
            out[(size_t)t0 * VOC + v0 + 8]       = acc[mt][nt][2] + bv8;
            out[(size_t)(t0 + 1) * VOC + v0 + 8] = acc[mt][nt][3] + bv8;
        }
    }
}

// =====================================================================
// launch
// =====================================================================
extern "C" void kernel_launch(void* const* d_in, const int* in_sizes, int n_in,
                              void* d_out, int out_size) {
    const int*   captions = (const int*)  d_in[0];
    const float* features = (const float*)d_in[1];
    const float* etab     = (const float*)d_in[2];
    const float* W_ih     = (const float*)d_in[3];
    const float* W_hh     = (const float*)d_in[4];
    const float* b_ih     = (const float*)d_in[5];
    const float* b_hh     = (const float*)d_in[6];
    const float* fc_W     = (const float*)d_in[7];
    const float* fc_b     = (const float*)d_in[8];
    float* out = (float*)d_out;

    cudaFuncSetAttribute(fc_mma_kernel,
                         cudaFuncAttributeMaxDynamicSharedMemorySize, FC_SMEM);

    prep_kernel<<<T_STEPS, 256>>>(captions, features, etab);
    lstm_kernel<<<NBLK, 512>>>(W_ih, W_hh, b_ih, b_hh);
    fc_mma_kernel<<<VOC / FC_M, 128, FC_SMEM>>>(fc_W, fc_b, out);
}